// round 12
// baseline (speedup 1.0000x reference)
#include <cuda_runtime.h>
#include <cstdint>

// Problem constants: preds/targets are (256, 3, 256, 256) fp32.
#define NROWS    256
#define DLEN     196608              // 3*256*256 elements per row
#define D4       (DLEN / 4)          // 49152 float4 per row
#define SPLITS   8                   // blocks per row
#define CHUNK4   (D4 / SPLITS)       // 6144 float4 per block
#define TPB      512
#define NWARP    (TPB / 32)          // 16
#define NBLOCKS  (NROWS * SPLITS)    // 2048

#define STAGES   4
#define STG4     512                 // float4 per stream per stage (1 per thread)
#define STG_B    (STG4 * 16)         // 8192 bytes per stream per stage
#define NITER    (CHUNK4 / STG4)     // 12 iterations per block

__device__ double g_part[NROWS * SPLITS * 5];
__device__ unsigned int g_done;      // self-wrapping counter (atomicInc mod NBLOCKS)

__device__ __forceinline__ double warp_reduce(double v) {
    #pragma unroll
    for (int off = 16; off > 0; off >>= 1)
        v += __shfl_down_sync(0xffffffffu, v, off);
    return v;
}

__device__ __forceinline__ uint32_t smem_u32(const void* p) {
    return (uint32_t)__cvta_generic_to_shared(p);
}

__device__ __forceinline__ void mbar_init(uint32_t mbar, uint32_t count) {
    asm volatile("mbarrier.init.shared.b64 [%0], %1;" :: "r"(mbar), "r"(count) : "memory");
}
__device__ __forceinline__ void mbar_expect_tx(uint32_t mbar, uint32_t bytes) {
    asm volatile("mbarrier.arrive.expect_tx.shared.b64 _, [%0], %1;"
                 :: "r"(mbar), "r"(bytes) : "memory");
}
__device__ __forceinline__ void mbar_wait(uint32_t mbar, uint32_t parity) {
    asm volatile(
        "{\n\t"
        ".reg .pred P;\n\t"
        "WAITLOOP_%=:\n\t"
        "mbarrier.try_wait.parity.acquire.cta.shared::cta.b64 P, [%0], %1, 0x989680;\n\t"
        "@P bra.uni WAITDONE_%=;\n\t"
        "bra.uni WAITLOOP_%=;\n\t"
        "WAITDONE_%=:\n\t"
        "}" :: "r"(mbar), "r"(parity) : "memory");
}
__device__ __forceinline__ void bulk_g2s(uint32_t dst, const void* src,
                                         uint32_t bytes, uint32_t mbar) {
    asm volatile(
        "cp.async.bulk.shared::cta.global.mbarrier::complete_tx::bytes [%0], [%1], %2, [%3];"
        :: "r"(dst), "l"(src), "r"(bytes), "r"(mbar) : "memory");
}

__global__ void __launch_bounds__(TPB)
pixcorr_bulk(const float4* __restrict__ preds,
             const float4* __restrict__ targs,
             float* __restrict__ out) {
    __shared__ __align__(16) float4 s_p[STAGES][STG4];   // 32 KB
    __shared__ __align__(16) float4 s_t[STAGES][STG4];   // 32 KB
    __shared__ __align__(8)  unsigned long long s_mbar[STAGES];
    __shared__ double red_s[NWARP][5];
    __shared__ bool is_last;

    const int tid  = threadIdx.x;
    const int lane = tid & 31;
    const int warp = tid >> 5;
    const int row   = blockIdx.y;
    const int chunk = blockIdx.x;
    const size_t base = (size_t)row * D4 + (size_t)chunk * CHUNK4;
    const float4* __restrict__ p = preds + base;  // B
    const float4* __restrict__ t = targs + base;  // Z

    if (tid == 0) {
        #pragma unroll
        for (int s = 0; s < STAGES; s++)
            mbar_init(smem_u32(&s_mbar[s]), 1);
        asm volatile("fence.proxy.async.shared::cta;" ::: "memory");
    }
    __syncthreads();

    // Prologue: fill all stages (64 KB in flight per block).
    if (tid == 0) {
        #pragma unroll
        for (int s = 0; s < STAGES; s++) {
            uint32_t mb = smem_u32(&s_mbar[s]);
            mbar_expect_tx(mb, 2 * STG_B);
            bulk_g2s(smem_u32(&s_p[s][0]), p + s * STG4, STG_B, mb);
            bulk_g2s(smem_u32(&s_t[s][0]), t + s * STG4, STG_B, mb);
        }
    }

    float sz = 0.f, sb = 0.f, szz = 0.f, sbb = 0.f, szb = 0.f;

    for (int it = 0; it < NITER; it++) {
        const int slot = it & (STAGES - 1);
        const uint32_t parity = (it / STAGES) & 1;
        mbar_wait(smem_u32(&s_mbar[slot]), parity);

        // One float4 per stream per thread; pull to regs, release slot,
        // issue refill, then FMA burst overlaps the in-flight copy.
        float4 a = s_p[slot][tid];
        float4 b = s_t[slot][tid];
        __syncthreads();
        if (tid == 0 && it + STAGES < NITER) {
            const int nxt = it + STAGES;
            uint32_t mb = smem_u32(&s_mbar[slot]);
            mbar_expect_tx(mb, 2 * STG_B);
            bulk_g2s(smem_u32(&s_p[slot][0]), p + (size_t)nxt * STG4, STG_B, mb);
            bulk_g2s(smem_u32(&s_t[slot][0]), t + (size_t)nxt * STG4, STG_B, mb);
        }

        sz += (b.x + b.y) + (b.z + b.w);
        sb += (a.x + a.y) + (a.z + a.w);
        szz = fmaf(b.x, b.x, szz); szz = fmaf(b.y, b.y, szz);
        szz = fmaf(b.z, b.z, szz); szz = fmaf(b.w, b.w, szz);
        sbb = fmaf(a.x, a.x, sbb); sbb = fmaf(a.y, a.y, sbb);
        sbb = fmaf(a.z, a.z, sbb); sbb = fmaf(a.w, a.w, sbb);
        szb = fmaf(b.x, a.x, szb); szb = fmaf(b.y, a.y, szb);
        szb = fmaf(b.z, a.z, szb); szb = fmaf(b.w, a.w, szb);
    }

    // ---- block reduction (fp64 from here) ----
    double v[5] = { (double)sz, (double)sb, (double)szz, (double)sbb, (double)szb };
    #pragma unroll
    for (int k = 0; k < 5; k++) {
        double r = warp_reduce(v[k]);
        if (lane == 0) red_s[warp][k] = r;
    }
    __syncthreads();
    if (warp == 0) {
        #pragma unroll
        for (int k = 0; k < 5; k++) {
            double r = (lane < NWARP) ? red_s[lane][k] : 0.0;
            r = warp_reduce(r);
            if (lane == 0)
                g_part[((size_t)row * SPLITS + chunk) * 5 + k] = r;
        }
    }

    // ---- last-block finalization ----
    if (tid == 0) {
        __threadfence();
        unsigned int prev = atomicInc(&g_done, NBLOCKS - 1);
        is_last = (prev == NBLOCKS - 1);
    }
    __syncthreads();
    if (!is_last) return;

    // One thread per row for the first NROWS threads.
    double corr = 0.0;
    if (tid < NROWS) {
        const int r = tid;
        double s0 = 0.0, s1 = 0.0, s2 = 0.0, s3 = 0.0, s4 = 0.0;
        #pragma unroll
        for (int c = 0; c < SPLITS; c++) {
            const double* g = &g_part[((size_t)r * SPLITS + c) * 5];
            s0 += g[0]; s1 += g[1]; s2 += g[2]; s3 += g[3]; s4 += g[4];
        }
        const double Dd = (double)DLEN;
        double num = s4 - s0 * s1 / Dd;
        double vz  = s2 - s0 * s0 / Dd; if (vz < 0.0) vz = 0.0;
        double vb  = s3 - s1 * s1 / Dd; if (vb < 0.0) vb = 0.0;
        corr = num / (sqrt(vz) * sqrt(vb) + 1e-6);
    }

    __shared__ double fin_s[NWARP];
    double rsum = warp_reduce(corr);
    if (lane == 0) fin_s[warp] = rsum;
    __syncthreads();
    if (warp == 0) {
        double rr = (lane < NWARP) ? fin_s[lane] : 0.0;
        rr = warp_reduce(rr);
        if (lane == 0)
            *out = (float)(rr / (double)NROWS);
    }
}

extern "C" void kernel_launch(void* const* d_in, const int* in_sizes, int n_in,
                              void* d_out, int out_size) {
    const float4* preds = (const float4*)d_in[0];
    const float4* targs = (const float4*)d_in[1];
    float* out = (float*)d_out;

    dim3 grid(SPLITS, NROWS);
    pixcorr_bulk<<<grid, TPB>>>(preds, targs, out);
}

// round 14
// speedup vs baseline: 1.3175x; 1.3175x over previous
#include <cuda_runtime.h>

// Problem constants: preds/targets are (256, 3, 256, 256) fp32.
#define NROWS    256
#define DLEN     196608            // 3*256*256 elements per row
#define D4       (DLEN / 4)        // 49152 float4 per row
#define SPLITS   4                 // blocks per row -> 1024 blocks = ONE wave
#define CHUNK4   (D4 / SPLITS)     // 12288 float4 per block
#define TPB      256
#define NBLOCKS  (NROWS * SPLITS)  // 1024

// Per-(row,chunk) partial sums: [sz, sb, szz, sbb, szb] in double.
// Fully overwritten every launch -> deterministic.
__device__ double g_part[NROWS * SPLITS * 5];
// Self-wrapping completion counter: atomicInc(.., NBLOCKS-1) returns to 0
// after the last block, so every graph replay starts from 0.
__device__ unsigned int g_done;

__device__ __forceinline__ double warp_reduce(double v) {
    #pragma unroll
    for (int off = 16; off > 0; off >>= 1)
        v += __shfl_down_sync(0xffffffffu, v, off);
    return v;
}

// Plain launch bounds, regs ~32, high occupancy: the R2 configuration that
// measured 5.0 TB/s — the best of 7 profiled variants.
__global__ void __launch_bounds__(TPB)
pixcorr_fused(const float4* __restrict__ preds,
              const float4* __restrict__ targs,
              float* __restrict__ out) {
    const int row   = blockIdx.y;
    const int chunk = blockIdx.x;
    const size_t base = (size_t)row * D4 + (size_t)chunk * CHUNK4;
    const float4* __restrict__ p = preds + base;  // B
    const float4* __restrict__ t = targs + base;  // Z

    float sz = 0.f, sb = 0.f, szz = 0.f, sbb = 0.f, szb = 0.f;

    // 48 iterations per thread, unroll 4 (R2's exact loop shape).
    #pragma unroll 4
    for (int i = threadIdx.x; i < CHUNK4; i += TPB) {
        float4 a = p[i];
        float4 b = t[i];
        sz += (b.x + b.y) + (b.z + b.w);
        sb += (a.x + a.y) + (a.z + a.w);
        szz = fmaf(b.x, b.x, szz); szz = fmaf(b.y, b.y, szz);
        szz = fmaf(b.z, b.z, szz); szz = fmaf(b.w, b.w, szz);
        sbb = fmaf(a.x, a.x, sbb); sbb = fmaf(a.y, a.y, sbb);
        sbb = fmaf(a.z, a.z, sbb); sbb = fmaf(a.w, a.w, sbb);
        szb = fmaf(b.x, a.x, szb); szb = fmaf(b.y, a.y, szb);
        szb = fmaf(b.z, a.z, szb); szb = fmaf(b.w, a.w, szb);
    }

    double v[5] = { (double)sz, (double)sb, (double)szz, (double)sbb, (double)szb };

    __shared__ double smem[TPB / 32][5];
    const int lane = threadIdx.x & 31;
    const int warp = threadIdx.x >> 5;

    #pragma unroll
    for (int k = 0; k < 5; k++) {
        double r = warp_reduce(v[k]);
        if (lane == 0) smem[warp][k] = r;
    }
    __syncthreads();

    if (warp == 0) {
        #pragma unroll
        for (int k = 0; k < 5; k++) {
            double r = (lane < TPB / 32) ? smem[lane][k] : 0.0;
            r = warp_reduce(r);
            if (lane == 0)
                g_part[((size_t)row * SPLITS + chunk) * 5 + k] = r;
        }
    }

    // ---- last-block finalization (replaces a 13us second graph node) ----
    __shared__ bool is_last;
    if (threadIdx.x == 0) {
        __threadfence();           // order thread 0's g_part stores
        unsigned int prev = atomicInc(&g_done, NBLOCKS - 1);
        is_last = (prev == NBLOCKS - 1);   // counter wrapped back to 0
    }
    __syncthreads();
    if (!is_last) return;

    // One thread per row; partials are L2-resident (just written + fenced).
    const int r = threadIdx.x;
    double s0 = 0.0, s1 = 0.0, s2 = 0.0, s3 = 0.0, s4 = 0.0;
    #pragma unroll
    for (int c = 0; c < SPLITS; c++) {
        const double* g = &g_part[((size_t)r * SPLITS + c) * 5];
        s0 += g[0]; s1 += g[1]; s2 += g[2]; s3 += g[3]; s4 += g[4];
    }

    const double Dd = (double)DLEN;
    double num = s4 - s0 * s1 / Dd;
    double vz  = s2 - s0 * s0 / Dd; if (vz < 0.0) vz = 0.0;
    double vb  = s3 - s1 * s1 / Dd; if (vb < 0.0) vb = 0.0;
    double corr = num / (sqrt(vz) * sqrt(vb) + 1e-6);

    __shared__ double red_s[TPB / 32];
    double rsum = warp_reduce(corr);
    if (lane == 0) red_s[warp] = rsum;
    __syncthreads();
    if (warp == 0) {
        double rr = (lane < TPB / 32) ? red_s[lane] : 0.0;
        rr = warp_reduce(rr);
        if (lane == 0)
            *out = (float)(rr / (double)NROWS);
    }
}

extern "C" void kernel_launch(void* const* d_in, const int* in_sizes, int n_in,
                              void* d_out, int out_size) {
    const float4* preds = (const float4*)d_in[0];
    const float4* targs = (const float4*)d_in[1];
    float* out = (float*)d_out;

    dim3 grid(SPLITS, NROWS);
    pixcorr_fused<<<grid, TPB>>>(preds, targs, out);
}